// round 7
// baseline (speedup 1.0000x reference)
#include <cuda_runtime.h>
#include <cuda_fp16.h>
#include <cstdint>

#define H 65536
#define C 384
#define S 1024

// scratch: d_acc layout [S][C][2] = interleaved (num, den)
__device__ float d_acc[S * C * 2];
__device__ float d_z[S * C];
__device__ int   d_is64;

__device__ __forceinline__ uint32_t smem_u32(const void* p) {
    uint32_t a;
    asm("{ .reg .u64 t; cvta.to.shared.u64 t, %1; cvt.u32.u64 %0, t; }" : "=r"(a) : "l"(p));
    return a;
}

__device__ __forceinline__ uint32_t pack_h2(float a, float b) {
    __half2 h = __floats2half2_rn(a, b);
    return *(uint32_t*)&h;
}

__device__ __forceinline__ void mma16(float& c0, float& c1, float& c2, float& c3,
                                      uint32_t a0, uint32_t a1, uint32_t a2, uint32_t a3,
                                      uint32_t b0, uint32_t b1) {
    asm volatile(
        "mma.sync.aligned.m16n8k16.row.col.f32.f16.f16.f32 "
        "{%0,%1,%2,%3}, {%4,%5,%6,%7}, {%8,%9}, {%0,%1,%2,%3};\n"
        : "+f"(c0), "+f"(c1), "+f"(c2), "+f"(c3)
        : "r"(a0), "r"(a1), "r"(a2), "r"(a3), "r"(b0), "r"(b1));
}

__device__ __forceinline__ void ldsm4(uint32_t& r0, uint32_t& r1, uint32_t& r2, uint32_t& r3,
                                      uint32_t addr) {
    asm volatile("ldmatrix.sync.aligned.m8n8.x4.shared.b16 {%0,%1,%2,%3}, [%4];"
                 : "=r"(r0), "=r"(r1), "=r"(r2), "=r"(r3) : "r"(addr));
}

__device__ __forceinline__ void ldsm2(uint32_t& r0, uint32_t& r1, uint32_t addr) {
    asm volatile("ldmatrix.sync.aligned.m8n8.x2.shared.b16 {%0,%1}, [%2];"
                 : "=r"(r0), "=r"(r1) : "r"(addr));
}

__device__ __forceinline__ void red4(float* p, float a, float b, float c, float d) {
    asm volatile("red.global.add.v4.f32 [%0], {%1,%2,%3,%4};"
                 :: "l"(p), "f"(a), "f"(b), "f"(c), "f"(d) : "memory");
}

__device__ __forceinline__ float clamp50(float v) {
    return fminf(fmaxf(v, -50.0f), 50.0f);
}

__device__ __forceinline__ int seg_at(const void* ix, int i, int is64) {
    int v = is64 ? (int)((const long long*)ix)[i] : ((const int*)ix)[i];
    return min(max(v, 0), S - 1);
}

// ---------------------------------------------------------------------------
// Kernel 0: zero accumulator + (last block) detect ix dtype
// ---------------------------------------------------------------------------
#define ZBLOCKS (2 * S * C / 256)
__global__ void zero_detect_kernel(const void* ix) {
    if (blockIdx.x < ZBLOCKS) {
        int i = blockIdx.x * 256 + threadIdx.x;
        d_acc[i] = 0.0f;
        return;
    }
    __shared__ int bad;
    if (threadIdx.x == 0) bad = 0;
    __syncthreads();
    const long long* p = (const long long*)ix;
    int local = 0;
    for (int i = threadIdx.x; i < 32768; i += 256) {
        long long v = p[i];
        if (v < 0 || v >= S) local = 1;
    }
    if (local) bad = 1;
    __syncthreads();
    if (threadIdx.x == 0) d_is64 = bad ? 0 : 1;
}

// ---------------------------------------------------------------------------
// Kernel 1: fused fx/gx GEMMs (fp16 mma, fp32 accum) + exp + segment red.
// CTA: 64 rows, grid 1024 (148 slots @ occ 1 -> 6.92 waves, 1.2% quantization
// waste vs 15.6% at grid 256). 512 threads = 16 warps, warp grid
// 2(M, 32 rows) x 8(N, 8 cols of f AND g). K chunks of 32, ping-pong weight
// buffers, one sync per chunk. Fragments via ldmatrix (2x x4 A, 2x x2 B).
// smem padded to 116KB to pin occupancy at 1 (wave math requires it).
// Epilogue: red.global.add.v4 {num,den,num,den} per 2 cols.
// ---------------------------------------------------------------------------
#define BM 64
#define XSTRH 196   // x row stride in words (192 + 4 pad)
#define WSTRH 20    // weight row stride in words (16 + 4 pad)

#define XS_W     (BM * XSTRH)            // 12544 words
#define WB_W     2560                    // one ping-pong buffer: f(1280)+g(1280)
#define WBUF_W   XS_W
#define SEGS_W   (XS_W + 2 * WB_W)       // 17664
#define SMEM_FG  118784                  // 116 KB: forces occupancy 1

__global__ __launch_bounds__(512, 1) void fused_fg_kernel(
    const float* __restrict__ x, const void* __restrict__ ix,
    const float* __restrict__ f_w, const float* __restrict__ f_b,
    const float* __restrict__ g_w, const float* __restrict__ g_b) {
    extern __shared__ uint32_t sm[];
    int* segs = (int*)(sm + SEGS_W);
    const uint32_t xsb = smem_u32(sm);

    const int tid = threadIdx.x;
    const int lane = tid & 31;
    const int warp = tid >> 5;
    const int wm = warp >> 3;   // 0..1 (32 rows each)
    const int wn = warp & 7;    // 0..7 (8-col strip, f and g)
    const int q = lane & 3;
    const int p = lane >> 2;
    const int blockRow = blockIdx.x * BM;

    const int is64 = d_is64;
    if (tid < BM) segs[tid] = seg_at(ix, blockRow + tid, is64);

    // load x tile [64 x 384] -> half2 smem
    for (int i = tid; i < BM * (C / 4); i += 512) {
        int r = i / (C / 4), c4 = i % (C / 4);
        float4 v = *(const float4*)(x + (size_t)(blockRow + r) * C + c4 * 4);
        uint32_t* dst = sm + r * XSTRH + c4 * 2;
        dst[0] = pack_h2(v.x, v.y);
        dst[1] = pack_h2(v.z, v.w);
    }

    // ldmatrix lane-address offsets (bytes)
    const int lm = lane >> 3;      // 0..3
    const int li = lane & 7;
    // A x4: m=lm: row = wm*32 + mt*16 + (m&1)*8 + li, colword = (m>>1)*4
    uint32_t aOff0 = (uint32_t)(((wm * 32 + ((lm & 1) << 3) + li) * XSTRH + ((lm >> 1) << 2)) * 4);
    uint32_t aOff1 = aOff0 + (uint32_t)(16 * XSTRH * 4);
    // B x2: m = lane>>3 & 1: row = wn*8 + li, colword = m*4
    uint32_t bOff = (uint32_t)(((wn * 8 + li) * WSTRH + ((lm & 1) << 2)) * 4);

    const int wrow = tid >> 3;      // 0..63: weight row within np-tile
    const int kq = tid & 7;

    for (int np = 0; np < 6; ++np) {
        float accf[2][4];
        float accg[2][4];
        #pragma unroll
        for (int a = 0; a < 2; a++)
            #pragma unroll
            for (int b = 0; b < 4; b++) { accf[a][b] = 0.0f; accg[a][b] = 0.0f; }

        const float* fW = f_w + (size_t)(np * 64) * C + (size_t)wrow * C + kq * 4;
        const float* gW = g_w + (size_t)(np * 64) * C + (size_t)wrow * C + kq * 4;

        // stage chunk 0 into buffer 0
        {
            float4 rf = *(const float4*)(fW);
            float4 rg = *(const float4*)(gW);
            uint32_t* d0 = sm + WBUF_W + wrow * WSTRH + kq * 2;
            d0[0] = pack_h2(rf.x, rf.y); d0[1] = pack_h2(rf.z, rf.w);
            uint32_t* e0 = d0 + 1280;
            e0[0] = pack_h2(rg.x, rg.y); e0[1] = pack_h2(rg.z, rg.w);
        }
        float4 rf = *(const float4*)(fW + 32);
        float4 rg = *(const float4*)(gW + 32);
        __syncthreads();

        for (int kc = 0; kc < 12; ++kc) {
            const int b = kc & 1;
            if (kc < 11) {  // stage chunk kc+1 into the other buffer
                uint32_t* d0 = sm + WBUF_W + (b ^ 1) * WB_W + wrow * WSTRH + kq * 2;
                d0[0] = pack_h2(rf.x, rf.y); d0[1] = pack_h2(rf.z, rf.w);
                uint32_t* e0 = d0 + 1280;
                e0[0] = pack_h2(rg.x, rg.y); e0[1] = pack_h2(rg.z, rg.w);
                if (kc < 10) {
                    rf = *(const float4*)(fW + (kc + 2) * 32);
                    rg = *(const float4*)(gW + (kc + 2) * 32);
                }
            }
            const uint32_t fb = xsb + (WBUF_W + b * WB_W) * 4;
            const uint32_t gb = fb + 1280 * 4;
            const uint32_t aKw = xsb + (uint32_t)(kc * 64);
            #pragma unroll
            for (int kk = 0; kk < 2; ++kk) {
                const uint32_t kb = (uint32_t)(kk * 32);
                uint32_t A0[4], A1[4], bf0, bf1, bg0, bg1;
                ldsm4(A0[0], A0[1], A0[2], A0[3], aKw + aOff0 + kb);
                ldsm4(A1[0], A1[1], A1[2], A1[3], aKw + aOff1 + kb);
                ldsm2(bf0, bf1, fb + bOff + kb);
                ldsm2(bg0, bg1, gb + bOff + kb);
                mma16(accf[0][0], accf[0][1], accf[0][2], accf[0][3],
                      A0[0], A0[1], A0[2], A0[3], bf0, bf1);
                mma16(accg[0][0], accg[0][1], accg[0][2], accg[0][3],
                      A0[0], A0[1], A0[2], A0[3], bg0, bg1);
                mma16(accf[1][0], accf[1][1], accf[1][2], accf[1][3],
                      A1[0], A1[1], A1[2], A1[3], bf0, bf1);
                mma16(accg[1][0], accg[1][1], accg[1][2], accg[1][3],
                      A1[0], A1[1], A1[2], A1[3], bg0, bg1);
            }
            __syncthreads();
        }

        // epilogue: w = exp(clip(gx+gb)), num = (fx+fb)*w; red4 per 2 cols
        {
            int col = np * 64 + wn * 8 + q * 2;
            float fb0 = __ldg(f_b + col), fb1 = __ldg(f_b + col + 1);
            float gb0 = __ldg(g_b + col), gb1 = __ldg(g_b + col + 1);
            #pragma unroll
            for (int mt = 0; mt < 2; ++mt) {
                int rloc = wm * 32 + mt * 16 + p;
                int s0 = segs[rloc];
                int s1 = segs[rloc + 8];
                float w00 = __expf(clamp50(accg[mt][0] + gb0));
                float w01 = __expf(clamp50(accg[mt][1] + gb1));
                float w10 = __expf(clamp50(accg[mt][2] + gb0));
                float w11 = __expf(clamp50(accg[mt][3] + gb1));
                float p00 = (accf[mt][0] + fb0) * w00;
                float p01 = (accf[mt][1] + fb1) * w01;
                float p10 = (accf[mt][2] + fb0) * w10;
                float p11 = (accf[mt][3] + fb1) * w11;
                red4(d_acc + (size_t)s0 * (2 * C) + col * 2, p00, w00, p01, w01);
                red4(d_acc + (size_t)s1 * (2 * C) + col * 2, p10, w10, p11, w11);
            }
        }
    }
}

// ---------------------------------------------------------------------------
// Kernel 2: z = (num/max(den,1e-9)) @ h_w^T + h_b over 1024 seg rows (fp16)
// grid 192 = 32 M-tiles (32 rows) x 6 N-slices (64 cols). Full K resident.
// ---------------------------------------------------------------------------
#define HRS 196
#define SMEM_H ((32 * HRS + 64 * HRS) * 4)   // 75264 bytes

__global__ __launch_bounds__(256, 2) void hgemm_kernel(
    const float* __restrict__ h_w, const float* __restrict__ h_b) {
    extern __shared__ uint32_t sm[];
    uint32_t* as_ = sm;
    uint32_t* whs = sm + 32 * HRS;

    const int tid = threadIdx.x;
    const int lane = tid & 31;
    const int warp = tid >> 5;
    const int wm = warp >> 2;   // 0..1
    const int wn = warp & 3;    // 0..3
    const int q = lane & 3;
    const int p = lane >> 2;
    const int blockRow = (blockIdx.x / 6) * 32;
    const int ns = blockIdx.x % 6;

    for (int i = tid; i < 32 * 96; i += 256) {
        int r = i / 96, c4g = i % 96;
        const float* src = d_acc + (size_t)(blockRow + r) * (2 * C) + c4g * 8;
        float4 v0 = *(const float4*)(src);
        float4 v1 = *(const float4*)(src + 4);
        uint32_t* dst = as_ + r * HRS + c4g * 2;
        dst[0] = pack_h2(v0.x / fmaxf(v0.y, 1e-9f), v0.z / fmaxf(v0.w, 1e-9f));
        dst[1] = pack_h2(v1.x / fmaxf(v1.y, 1e-9f), v1.z / fmaxf(v1.w, 1e-9f));
    }
    for (int i = tid; i < 64 * 96; i += 256) {
        int n = i / 96, c4 = i % 96;
        float4 v = *(const float4*)(h_w + (size_t)(ns * 64 + n) * C + c4 * 4);
        uint32_t* dst = whs + n * HRS + c4 * 2;
        dst[0] = pack_h2(v.x, v.y);
        dst[1] = pack_h2(v.z, v.w);
    }
    __syncthreads();

    float acc[2][4];
    #pragma unroll
    for (int a = 0; a < 2; a++)
        #pragma unroll
        for (int b = 0; b < 4; b++) acc[a][b] = 0.0f;

    const int r0 = wm * 16 + p;
    #pragma unroll 4
    for (int ks = 0; ks < 24; ++ks) {
        const int kw = ks * 8;
        uint32_t a0 = as_[r0 * HRS + kw + q];
        uint32_t a1 = as_[(r0 + 8) * HRS + kw + q];
        uint32_t a2 = as_[r0 * HRS + kw + q + 4];
        uint32_t a3 = as_[(r0 + 8) * HRS + kw + q + 4];
        #pragma unroll
        for (int nt = 0; nt < 2; ++nt) {
            int nb = wn * 16 + nt * 8 + p;
            uint32_t b0 = whs[nb * HRS + kw + q];
            uint32_t b1 = whs[nb * HRS + kw + q + 4];
            mma16(acc[nt][0], acc[nt][1], acc[nt][2], acc[nt][3], a0, a1, a2, a3, b0, b1);
        }
    }

    int s0 = blockRow + wm * 16 + p;
    int s1 = s0 + 8;
    #pragma unroll
    for (int nt = 0; nt < 2; ++nt) {
        int col = ns * 64 + wn * 16 + nt * 8 + q * 2;
        float hb0 = __ldg(h_b + col), hb1 = __ldg(h_b + col + 1);
        *(float2*)(d_z + (size_t)s0 * C + col) = make_float2(acc[nt][0] + hb0, acc[nt][1] + hb1);
        *(float2*)(d_z + (size_t)s1 * C + col) = make_float2(acc[nt][2] + hb0, acc[nt][3] + hb1);
    }
}

// ---------------------------------------------------------------------------
// Kernel 3: scatter y[h,:] = z[ix[h],:]
// ---------------------------------------------------------------------------
__global__ __launch_bounds__(256) void scatter_kernel(
    const void* __restrict__ ix, float* __restrict__ y) {
    __shared__ int segs[32];
    int tid = threadIdx.x;
    int base = blockIdx.x * 32;
    const int is64 = d_is64;
    if (tid < 32) segs[tid] = seg_at(ix, base + tid, is64);
    __syncthreads();
    for (int i = tid; i < 32 * 96; i += 256) {
        int r = i / 96, c4 = i % 96;
        float4 v = *(const float4*)(d_z + (size_t)segs[r] * C + c4 * 4);
        *(float4*)(y + ((size_t)(base + r)) * C + c4 * 4) = v;
    }
}

// ---------------------------------------------------------------------------
extern "C" void kernel_launch(void* const* d_in, const int* in_sizes, int n_in,
                              void* d_out, int out_size) {
    const float* x   = (const float*)d_in[0];
    const void*  ix  = d_in[1];
    const float* f_w = (const float*)d_in[2];
    const float* f_b = (const float*)d_in[3];
    const float* g_w = (const float*)d_in[4];
    const float* g_b = (const float*)d_in[5];
    const float* h_w = (const float*)d_in[6];
    const float* h_b = (const float*)d_in[7];
    float* y = (float*)d_out;

    cudaFuncSetAttribute(fused_fg_kernel, cudaFuncAttributeMaxDynamicSharedMemorySize, SMEM_FG);
    cudaFuncSetAttribute(hgemm_kernel, cudaFuncAttributeMaxDynamicSharedMemorySize, SMEM_H);

    zero_detect_kernel<<<ZBLOCKS + 1, 256>>>(ix);
    fused_fg_kernel<<<H / BM, 512, SMEM_FG>>>(x, ix, f_w, f_b, g_w, g_b);
    hgemm_kernel<<<192, 256, SMEM_H>>>(h_w, h_b);
    scatter_kernel<<<H / 32, 256>>>(ix, y);
}

// round 9
// speedup vs baseline: 1.5387x; 1.5387x over previous
#include <cuda_runtime.h>
#include <cuda_fp16.h>
#include <cstdint>

#define H 65536
#define C 384
#define S 1024

// scratch (allocation-free rule: device globals)
__device__ float d_acc[S * C * 2];        // [S][C][2] interleaved (num, den)
__device__ float d_z[S * C];
__device__ __half d_wh[2 * 384 * 384];    // fp16 weights: f then g
__device__ int   d_is64;

__device__ __forceinline__ uint32_t smem_u32(const void* p) {
    uint32_t a;
    asm("{ .reg .u64 t; cvta.to.shared.u64 t, %1; cvt.u32.u64 %0, t; }" : "=r"(a) : "l"(p));
    return a;
}

__device__ __forceinline__ uint32_t pack_h2(float a, float b) {
    __half2 h = __floats2half2_rn(a, b);
    return *(uint32_t*)&h;
}

__device__ __forceinline__ void mma16(float& c0, float& c1, float& c2, float& c3,
                                      uint32_t a0, uint32_t a1, uint32_t a2, uint32_t a3,
                                      uint32_t b0, uint32_t b1) {
    asm volatile(
        "mma.sync.aligned.m16n8k16.row.col.f32.f16.f16.f32 "
        "{%0,%1,%2,%3}, {%4,%5,%6,%7}, {%8,%9}, {%0,%1,%2,%3};\n"
        : "+f"(c0), "+f"(c1), "+f"(c2), "+f"(c3)
        : "r"(a0), "r"(a1), "r"(a2), "r"(a3), "r"(b0), "r"(b1));
}

__device__ __forceinline__ void ldsm4(uint32_t& r0, uint32_t& r1, uint32_t& r2, uint32_t& r3,
                                      uint32_t addr) {
    asm volatile("ldmatrix.sync.aligned.m8n8.x4.shared.b16 {%0,%1,%2,%3}, [%4];"
                 : "=r"(r0), "=r"(r1), "=r"(r2), "=r"(r3) : "r"(addr));
}

__device__ __forceinline__ void cp16(uint32_t dst, const void* src) {
    asm volatile("cp.async.cg.shared.global [%0], [%1], 16;" :: "r"(dst), "l"(src));
}
#define CP_COMMIT() asm volatile("cp.async.commit_group;" ::: "memory")

__device__ __forceinline__ void red4(float* p, float a, float b, float c, float d) {
    asm volatile("red.global.add.v4.f32 [%0], {%1,%2,%3,%4};"
                 :: "l"(p), "f"(a), "f"(b), "f"(c), "f"(d) : "memory");
}

__device__ __forceinline__ float clamp50(float v) {
    return fminf(fmaxf(v, -50.0f), 50.0f);
}

__device__ __forceinline__ int seg_at(const void* ix, int i, int is64) {
    int v = is64 ? (int)((const long long*)ix)[i] : ((const int*)ix)[i];
    return min(max(v, 0), S - 1);
}

// ---------------------------------------------------------------------------
// Kernel 0: zero accumulator | convert weights to fp16 | detect ix dtype
// ---------------------------------------------------------------------------
#define ZBLOCKS (2 * S * C / 256)       // 3072
#define CVT_BLOCKS 288                  // 2*384*384/4 float4 / 256
__global__ void prep_kernel(const void* ix, const float* fw, const float* gw) {
    int b = blockIdx.x;
    if (b < ZBLOCKS) {
        d_acc[b * 256 + threadIdx.x] = 0.0f;
        return;
    }
    if (b < ZBLOCKS + CVT_BLOCKS) {
        int j = (b - ZBLOCKS) * 256 + threadIdx.x;   // 0..73727 float4s
        const float* src = (j < 36864) ? fw + j * 4 : gw + (j - 36864) * 4;
        float4 v = *(const float4*)src;
        uint2 o;
        o.x = pack_h2(v.x, v.y);
        o.y = pack_h2(v.z, v.w);
        *(uint2*)((char*)d_wh + (size_t)j * 8) = o;
        return;
    }
    __shared__ int bad;
    if (threadIdx.x == 0) bad = 0;
    __syncthreads();
    const long long* p = (const long long*)ix;
    int local = 0;
    for (int i = threadIdx.x; i < 32768; i += 256) {
        long long v = p[i];
        if (v < 0 || v >= S) local = 1;
    }
    if (local) bad = 1;
    __syncthreads();
    if (threadIdx.x == 0) d_is64 = bad ? 0 : 1;
}

// ---------------------------------------------------------------------------
// Kernel 1: fused fx/gx GEMMs (fp16 mma, fp32 accum) + exp + segment red.
// CTA: 256 rows x full K=384 (half) resident; 512 threads = 16 warps,
// warp grid 8(M) x 2(N), warp tile 32x32 per matrix. 6 np-tiles of 64
// f-cols + 64 g-cols. K in chunks of 32; weight staging = ONE cp.async.cg
// 16B per thread per chunk from pre-converted d_wh, ping-pong buffers,
// one commit-group per chunk, wait_group 1 pipelining.
// Fragments via ldmatrix.x4. Epilogue: red.global.add.v4 per 2 cols.
// ---------------------------------------------------------------------------
#define BM 256
#define XSTRH 196   // x row stride in words (192 + 4 pad)
#define WSTRH 20    // weight row stride in words (16 + 4 pad)

#define XS_W     (BM * XSTRH)            // 50176 words
#define WB_W     2560                    // one buffer: f(1280)+g(1280) words
#define WBUF_W   XS_W
#define SEGS_W   (XS_W + 2 * WB_W)       // 55296
#define SMEM_FG  ((SEGS_W + BM) * 4)     // 222208 bytes (occ 1)

__global__ __launch_bounds__(512, 1) void fused_fg_kernel(
    const float* __restrict__ x, const void* __restrict__ ix,
    const float* __restrict__ f_b, const float* __restrict__ g_b) {
    extern __shared__ uint32_t sm[];
    int* segs = (int*)(sm + SEGS_W);
    const uint32_t xsb = smem_u32(sm);

    const int tid = threadIdx.x;
    const int lane = tid & 31;
    const int warp = tid >> 5;
    const int wm = warp >> 1;   // 0..7
    const int wn = warp & 1;    // 0..1
    const int q = lane & 3;
    const int p = lane >> 2;
    const int blockRow = blockIdx.x * BM;

    const int is64 = d_is64;
    if (tid < BM) segs[tid] = seg_at(ix, blockRow + tid, is64);

    // load x tile [256 x 384] -> half2 smem (once)
    for (int i = tid; i < BM * (C / 4); i += 512) {
        int r = i / (C / 4), c4 = i % (C / 4);
        float4 v = *(const float4*)(x + (size_t)(blockRow + r) * C + c4 * 4);
        uint32_t* dst = sm + r * XSTRH + c4 * 2;
        dst[0] = pack_h2(v.x, v.y);
        dst[1] = pack_h2(v.z, v.w);
    }

    // ldmatrix lane-address offsets (bytes)
    const int lm = lane >> 3;      // matrix id 0..3
    const int li = lane & 7;
    uint32_t aOff0 = (uint32_t)(((wm * 32 + ((lm & 1) << 3) + li) * XSTRH + ((lm >> 1) << 2)) * 4);
    uint32_t aOff1 = aOff0 + (uint32_t)(16 * XSTRH * 4);
    uint32_t bOff0 = (uint32_t)(((wn * 32 + ((lm >> 1) << 3) + li) * WSTRH + ((lm & 1) << 2)) * 4);
    uint32_t bOff1 = bOff0 + (uint32_t)(16 * WSTRH * 4);

    // cp.async mapping: each thread copies one 16B piece per chunk
    const int cm = tid >> 8;          // 0 = f, 1 = g
    const int cr = (tid >> 2) & 63;   // weight row 0..63
    const int cs = tid & 3;           // 16B segment within 64B row-chunk
    const __half* wsrc0 = d_wh + (size_t)cm * 147456 + (size_t)cr * 384 + cs * 8;
    const uint32_t wdst0 = xsb + (uint32_t)((WBUF_W + cm * 1280 + cr * WSTRH + cs * 4) * 4);

    for (int np = 0; np < 6; ++np) {
        float accf[2][4][4];
        float accg[2][4][4];
        #pragma unroll
        for (int a = 0; a < 2; a++)
            #pragma unroll
            for (int b = 0; b < 4; b++)
                #pragma unroll
                for (int c = 0; c < 4; c++) { accf[a][b][c] = 0.0f; accg[a][b][c] = 0.0f; }

        const __half* wsrc = wsrc0 + np * 64 * 384;

        // prologue: stage chunks 0 and 1
        cp16(wdst0, wsrc);                              CP_COMMIT();
        cp16(wdst0 + WB_W * 4, wsrc + 32);              CP_COMMIT();

        for (int kc = 0; kc < 12; ++kc) {
            const int b = kc & 1;
            if (kc == 11) asm volatile("cp.async.wait_group 0;" ::: "memory");
            else          asm volatile("cp.async.wait_group 1;" ::: "memory");
            __syncthreads();   // chunk kc visible to all; also fences x/segs staging

            const uint32_t fb = xsb + (WBUF_W + b * WB_W) * 4;
            const uint32_t gb = fb + 1280 * 4;
            const uint32_t aKw = xsb + (uint32_t)(kc * 64);
            #pragma unroll
            for (int kk = 0; kk < 2; ++kk) {
                const uint32_t kb = (uint32_t)(kk * 32);
                uint32_t A0[4], A1[4], F0[4], F1[4], G0[4], G1[4];
                ldsm4(A0[0], A0[1], A0[2], A0[3], aKw + aOff0 + kb);
                ldsm4(A1[0], A1[1], A1[2], A1[3], aKw + aOff1 + kb);
                ldsm4(F0[0], F0[1], F0[2], F0[3], fb + bOff0 + kb);
                ldsm4(F1[0], F1[1], F1[2], F1[3], fb + bOff1 + kb);
                ldsm4(G0[0], G0[1], G0[2], G0[3], gb + bOff0 + kb);
                ldsm4(G1[0], G1[1], G1[2], G1[3], gb + bOff1 + kb);
                #pragma unroll
                for (int nt = 0; nt < 4; ++nt) {
                    uint32_t bf0 = (nt < 2) ? F0[(nt & 1) * 2]     : F1[(nt & 1) * 2];
                    uint32_t bf1 = (nt < 2) ? F0[(nt & 1) * 2 + 1] : F1[(nt & 1) * 2 + 1];
                    uint32_t bg0 = (nt < 2) ? G0[(nt & 1) * 2]     : G1[(nt & 1) * 2];
                    uint32_t bg1 = (nt < 2) ? G0[(nt & 1) * 2 + 1] : G1[(nt & 1) * 2 + 1];
                    mma16(accf[0][nt][0], accf[0][nt][1], accf[0][nt][2], accf[0][nt][3],
                          A0[0], A0[1], A0[2], A0[3], bf0, bf1);
                    mma16(accg[0][nt][0], accg[0][nt][1], accg[0][nt][2], accg[0][nt][3],
                          A0[0], A0[1], A0[2], A0[3], bg0, bg1);
                    mma16(accf[1][nt][0], accf[1][nt][1], accf[1][nt][2], accf[1][nt][3],
                          A1[0], A1[1], A1[2], A1[3], bf0, bf1);
                    mma16(accg[1][nt][0], accg[1][nt][1], accg[1][nt][2], accg[1][nt][3],
                          A1[0], A1[1], A1[2], A1[3], bg0, bg1);
                }
            }
            __syncthreads();   // all readers done with buffer b before reuse
            if (kc + 2 < 12) {
                cp16(wdst0 + b * (WB_W * 4), wsrc + (kc + 2) * 32);
                CP_COMMIT();
            }
        }

        // epilogue: w = exp(clip(gx+gb)), num = (fx+fb)*w; red4 per 2 cols
        #pragma unroll
        for (int mt = 0; mt < 2; ++mt) {
            int rloc = wm * 32 + mt * 16 + p;
            int s0 = segs[rloc];
            int s1 = segs[rloc + 8];
            #pragma unroll
            for (int nt = 0; nt < 4; ++nt) {
                int col = np * 64 + wn * 32 + nt * 8 + q * 2;
                float fb0 = __ldg(f_b + col), fb1 = __ldg(f_b + col + 1);
                float gb0 = __ldg(g_b + col), gb1 = __ldg(g_b + col + 1);
                float w00 = __expf(clamp50(accg[mt][nt][0] + gb0));
                float w01 = __expf(clamp50(accg[mt][nt][1] + gb1));
                float w10 = __expf(clamp50(accg[mt][nt][2] + gb0));
                float w11 = __expf(clamp50(accg[mt][nt][3] + gb1));
                float p00 = (accf[mt][nt][0] + fb0) * w00;
                float p01 = (accf[mt][nt][1] + fb1) * w01;
                float p10 = (accf[mt][nt][2] + fb0) * w10;
                float p11 = (accf[mt][nt][3] + fb1) * w11;
                red4(d_acc + (size_t)s0 * (2 * C) + col * 2, p00, w00, p01, w01);
                red4(d_acc + (size_t)s1 * (2 * C) + col * 2, p10, w10, p11, w11);
            }
        }
        __syncthreads();   // epilogue/compute done before next np restages buffers
    }
}

// ---------------------------------------------------------------------------
// Kernel 2: z = (num/max(den,1e-9)) @ h_w^T + h_b over 1024 seg rows (fp16)
// grid 192 = 32 M-tiles (32 rows) x 6 N-slices (64 cols). Full K resident.
// ---------------------------------------------------------------------------
#define HRS 196
#define SMEM_H ((32 * HRS + 64 * HRS) * 4)   // 75264 bytes

__global__ __launch_bounds__(256, 2) void hgemm_kernel(
    const float* __restrict__ h_w, const float* __restrict__ h_b) {
    extern __shared__ uint32_t sm[];
    uint32_t* as_ = sm;
    uint32_t* whs = sm + 32 * HRS;

    const int tid = threadIdx.x;
    const int lane = tid & 31;
    const int warp = tid >> 5;
    const int wm = warp >> 2;
    const int wn = warp & 3;
    const int q = lane & 3;
    const int p = lane >> 2;
    const int blockRow = (blockIdx.x / 6) * 32;
    const int ns = blockIdx.x % 6;

    for (int i = tid; i < 32 * 96; i += 256) {
        int r = i / 96, c4g = i % 96;
        const float* src = d_acc + (size_t)(blockRow + r) * (2 * C) + c4g * 8;
        float4 v0 = *(const float4*)(src);
        float4 v1 = *(const float4*)(src + 4);
        uint32_t* dst = as_ + r * HRS + c4g * 2;
        dst[0] = pack_h2(v0.x / fmaxf(v0.y, 1e-9f), v0.z / fmaxf(v0.w, 1e-9f));
        dst[1] = pack_h2(v1.x / fmaxf(v1.y, 1e-9f), v1.z / fmaxf(v1.w, 1e-9f));
    }
    for (int i = tid; i < 64 * 96; i += 256) {
        int n = i / 96, c4 = i % 96;
        float4 v = *(const float4*)(h_w + (size_t)(ns * 64 + n) * C + c4 * 4);
        uint32_t* dst = whs + n * HRS + c4 * 2;
        dst[0] = pack_h2(v.x, v.y);
        dst[1] = pack_h2(v.z, v.w);
    }
    __syncthreads();

    float acc[2][4];
    #pragma unroll
    for (int a = 0; a < 2; a++)
        #pragma unroll
        for (int b = 0; b < 4; b++) acc[a][b] = 0.0f;

    const int r0 = wm * 16 + p;
    #pragma unroll 4
    for (int ks = 0; ks < 24; ++ks) {
        const int kw = ks * 8;
        uint32_t a0 = as_[r0 * HRS + kw + q];
        uint32_t a1 = as_[(r0 + 8) * HRS + kw + q];
        uint32_t a2 = as_[r0 * HRS + kw + q + 4];
        uint32_t a3 = as_[(r0 + 8) * HRS + kw + q + 4];
        #pragma unroll
        for (int nt = 0; nt < 2; ++nt) {
            int nb = wn * 16 + nt * 8 + p;
            uint32_t b0 = whs[nb * HRS + kw + q];
            uint32_t b1 = whs[nb * HRS + kw + q + 4];
            mma16(acc[nt][0], acc[nt][1], acc[nt][2], acc[nt][3], a0, a1, a2, a3, b0, b1);
        }
    }

    int s0 = blockRow + wm * 16 + p;
    int s1 = s0 + 8;
    #pragma unroll
    for (int nt = 0; nt < 2; ++nt) {
        int col = ns * 64 + wn * 16 + nt * 8 + q * 2;
        float hb0 = __ldg(h_b + col), hb1 = __ldg(h_b + col + 1);
        *(float2*)(d_z + (size_t)s0 * C + col) = make_float2(acc[nt][0] + hb0, acc[nt][1] + hb1);
        *(float2*)(d_z + (size_t)s1 * C + col) = make_float2(acc[nt][2] + hb0, acc[nt][3] + hb1);
    }
}

// ---------------------------------------------------------------------------
// Kernel 3: scatter y[h,:] = z[ix[h],:]
// ---------------------------------------------------------------------------
__global__ __launch_bounds__(256) void scatter_kernel(
    const void* __restrict__ ix, float* __restrict__ y) {
    __shared__ int segs[32];
    int tid = threadIdx.x;
    int base = blockIdx.x * 32;
    const int is64 = d_is64;
    if (tid < 32) segs[tid] = seg_at(ix, base + tid, is64);
    __syncthreads();
    for (int i = tid; i < 32 * 96; i += 256) {
        int r = i / 96, c4 = i % 96;
        float4 v = *(const float4*)(d_z + (size_t)segs[r] * C + c4 * 4);
        *(float4*)(y + ((size_t)(base + r)) * C + c4 * 4) = v;
    }
}

// ---------------------------------------------------------------------------
extern "C" void kernel_launch(void* const* d_in, const int* in_sizes, int n_in,
                              void* d_out, int out_size) {
    const float* x   = (const float*)d_in[0];
    const void*  ix  = d_in[1];
    const float* f_w = (const float*)d_in[2];
    const float* f_b = (const float*)d_in[3];
    const float* g_w = (const float*)d_in[4];
    const float* g_b = (const float*)d_in[5];
    const float* h_w = (const float*)d_in[6];
    const float* h_b = (const float*)d_in[7];
    float* y = (float*)d_out;

    cudaFuncSetAttribute(fused_fg_kernel, cudaFuncAttributeMaxDynamicSharedMemorySize, SMEM_FG);
    cudaFuncSetAttribute(hgemm_kernel, cudaFuncAttributeMaxDynamicSharedMemorySize, SMEM_H);

    prep_kernel<<<ZBLOCKS + CVT_BLOCKS + 1, 256>>>(ix, f_w, g_w);
    fused_fg_kernel<<<H / BM, 512, SMEM_FG>>>(x, ix, f_b, g_b);
    hgemm_kernel<<<192, 256, SMEM_H>>>(h_w, h_b);
    scatter_kernel<<<H / 32, 256>>>(ix, y);
}